// round 6
// baseline (speedup 1.0000x reference)
#include <cuda_runtime.h>
#include <stdint.h>

// Problem constants (fixed by reference: B=32, N=4096, D=128, E=24576)
#define BB 32
#define NN 4096
#define DD 128
#define EE 24576
#define BN (BB * NN)
#define NCHUNK 24          // EE / 1024

// Scratch (device globals: no allocation allowed in kernel_launch)
__device__ int   g_cnt[NCHUNK * NN];    // per-(chunk, node) histogram
__device__ int   g_offsets[NN + 1];
__device__ int   g_srcs[EE];            // src node per CSR slot (edge-id order)
__device__ float g_ssrc[BN];
__device__ float g_sdst[BN];            // includes bias
__device__ unsigned int g_bar;          // monotonic ticket barrier (never reset)

// ---------------------------------------------------------------------------
// k_build: fused CSR build, ONE kernel, grid = 24 blocks (always co-resident).
// Phase 1: per-chunk histogram -> g_cnt.   [grid-wide ticket barrier]
// Phase 2: totals + chunk-prefix + block scan -> offsets/cursors, then
// deterministic scatter (exact edge-id order within each dst bucket).
// ---------------------------------------------------------------------------
__global__ void __launch_bounds__(1024) k_build(const int* __restrict__ src,
                                                const int* __restrict__ dst) {
    __shared__ int h[NN];          // 16 KB: histogram, then cursors
    __shared__ int part[1024];     //  4 KB: scan partials
    int c = blockIdx.x, t = threadIdx.x;

    // ---- Phase 1: histogram of chunk c ----
    #pragma unroll
    for (int i = t; i < NN; i += 1024) h[i] = 0;
    __syncthreads();
    int e  = c * 1024 + t;
    int d  = dst[e];
    int sv = src[e];
    atomicAdd(&h[d], 1);
    __syncthreads();
    #pragma unroll
    for (int i = t; i < NN; i += 1024) g_cnt[c * NN + i] = h[i];

    // ---- grid barrier (24 blocks, all co-resident; monotonic ticket) ----
    __threadfence();
    __syncthreads();
    if (t == 0) {
        unsigned int ticket = atomicAdd(&g_bar, 1u);
        unsigned int target = (ticket / NCHUNK + 1u) * NCHUNK;
        while (*(volatile unsigned int*)&g_bar < target) { }
    }
    __syncthreads();
    __threadfence();

    // ---- Phase 2: totals + prefix-below-c (coalesced pass over g_cnt) ----
    int base = t * 4;
    int tot[4] = {0, 0, 0, 0};
    int pre[4] = {0, 0, 0, 0};
    #pragma unroll
    for (int cc = 0; cc < NCHUNK; cc++) {
        #pragma unroll
        for (int k = 0; k < 4; k++) {
            int v = g_cnt[cc * NN + base + k];
            tot[k] += v;
            if (cc < c) pre[k] += v;
        }
    }

    // block-wide exclusive scan of totals
    int s = tot[0] + tot[1] + tot[2] + tot[3];
    part[t] = s;
    __syncthreads();
    for (int off = 1; off < 1024; off <<= 1) {
        int add = (t >= off) ? part[t - off] : 0;
        __syncthreads();
        part[t] += add;
        __syncthreads();
    }
    int run = part[t] - s;
    #pragma unroll
    for (int k = 0; k < 4; k++) {
        if (c == 0) g_offsets[base + k] = run;
        h[base + k] = run + pre[k];    // chunk-c cursor for node base+k
        run += tot[k];
    }
    if (c == 0 && t == 1023) g_offsets[NN] = run;  // == EE
    __syncthreads();

    // ---- deterministic scatter of chunk c ----
    unsigned mask = __match_any_sync(0xFFFFFFFFu, d);
    int lane     = t & 31;
    int lanerank = __popc(mask & ((1u << lane) - 1));
    int cntm     = __popc(mask);
    int leader   = __ffs(mask) - 1;
    int wid      = t >> 5;

    int bpos = 0;
    #pragma unroll
    for (int w = 0; w < 32; w++) {
        if (wid == w && lane == leader) {
            bpos = h[d];
            h[d] = bpos + cntm;
        }
        __syncthreads();
    }
    bpos = __shfl_sync(0xFFFFFFFFu, bpos, leader);
    g_srcs[bpos + lanerank] = sv;
}

// ---------------------------------------------------------------------------
// Per-node projections: ssrc[b,n] = <x[b,n], Ws>, sdst[b,n] = <x[b,n], Wd>+bias.
// One warp per row; each lane owns one float4 (D=128 = 32 lanes * 4).
// ---------------------------------------------------------------------------
__global__ void k_dots(const float4* __restrict__ x4, const float4* __restrict__ W4,
                       const float* __restrict__ bias) {
    int wid  = (blockIdx.x * blockDim.x + threadIdx.x) >> 5;   // row in [0, B*N)
    int lane = threadIdx.x & 31;
    float4 xr = x4[(size_t)wid * 32 + lane];
    float4 ws = W4[lane];
    float4 wd = W4[32 + lane];
    float a = xr.x * ws.x + xr.y * ws.y + xr.z * ws.z + xr.w * ws.w;
    float c = xr.x * wd.x + xr.y * wd.y + xr.z * wd.z + xr.w * wd.w;
    #pragma unroll
    for (int o = 16; o > 0; o >>= 1) {
        a += __shfl_xor_sync(0xFFFFFFFFu, a, o);
        c += __shfl_xor_sync(0xFFFFFFFFu, c, o);
    }
    if (lane == 0) {
        g_ssrc[wid] = a;
        g_sdst[wid] = c + bias[0];
    }
}

__device__ __forceinline__ float sigmoidf_fast(float z) {
    return 1.0f / (1.0f + __expf(-z));
}

// ---------------------------------------------------------------------------
// Main gather kernel: one warp per (b, n) — maximal warp-level concurrency
// (131072 warps) to keep the L2 request queues saturated. 2-edge unroll with
// dual accumulators. Out stores use __stcs (evict-first) so the 67MB write
// stream doesn't displace L2-resident x.
// ---------------------------------------------------------------------------
__global__ void __launch_bounds__(256) k_main(const float4* __restrict__ x4,
                                              float4* __restrict__ out4) {
    int w    = (blockIdx.x * blockDim.x + threadIdx.x) >> 5;   // (b,n) pair
    int lane = threadIdx.x & 31;
    int b = w >> 12;            // / NN  (batch-major: wave shares x[b] in L2)
    int n = w & (NN - 1);

    const float4* xb = x4 + ((size_t)b * NN) * 32;
    const float*  ss = g_ssrc + b * NN;
    float sd = g_sdst[w];

    int lo = g_offsets[n], hi = g_offsets[n + 1];

    float4 p0 = make_float4(0.f, 0.f, 0.f, 0.f);
    float4 p1 = make_float4(0.f, 0.f, 0.f, 0.f);
    int j = lo;
    for (; j + 1 < hi; j += 2) {
        int s0 = g_srcs[j];
        int s1 = g_srcs[j + 1];
        float a0 = sigmoidf_fast(ss[s0] + sd);
        float a1 = sigmoidf_fast(ss[s1] + sd);
        float4 v0 = xb[(size_t)s0 * 32 + lane];
        float4 v1 = xb[(size_t)s1 * 32 + lane];
        p0.x += v0.x * a0; p0.y += v0.y * a0; p0.z += v0.z * a0; p0.w += v0.w * a0;
        p1.x += v1.x * a1; p1.y += v1.y * a1; p1.z += v1.z * a1; p1.w += v1.w * a1;
    }
    if (j < hi) {
        int s0 = g_srcs[j];
        float a0 = sigmoidf_fast(ss[s0] + sd);
        float4 v0 = xb[(size_t)s0 * 32 + lane];
        p0.x += v0.x * a0; p0.y += v0.y * a0; p0.z += v0.z * a0; p0.w += v0.w * a0;
    }
    p0.x += p1.x; p0.y += p1.y; p0.z += p1.z; p0.w += p1.w;

    __stcs(&out4[(size_t)w * 32 + lane], p0);
}

// ---------------------------------------------------------------------------
// Launch
// ---------------------------------------------------------------------------
extern "C" void kernel_launch(void* const* d_in, const int* in_sizes, int n_in,
                              void* d_out, int out_size) {
    const float* x    = (const float*)d_in[0];   // (B, N, D) f32
    const int*   ei   = (const int*)d_in[1];     // (2, E)    i32
    const float* W    = (const float*)d_in[2];   // (1, 2D)   f32
    const float* bias = (const float*)d_in[3];   // (1,)      f32
    float* out = (float*)d_out;                  // (B, N, D) f32

    const int* src = ei;        // edge_index[0]
    const int* dst = ei + EE;   // edge_index[1]

    k_build<<<NCHUNK, 1024>>>(src, dst);
    k_dots<<<BN / 8, 256>>>((const float4*)x, (const float4*)W, bias);
    k_main<<<BN / 8, 256>>>((const float4*)x, (float4*)out);
}